// round 1
// baseline (speedup 1.0000x reference)
#include <cuda_runtime.h>
#include <math.h>
#include <float.h>

#define BB 4
#define TT 1024
#define FF 1024
#define HH 16
#define DD 64
#define NR (BB*TT)        // 4096 rows

// ---------------- scratch (static device globals; no allocation) ----------------
__device__ float g_q[(size_t)NR * FF];
__device__ float g_k[(size_t)NR * FF];
__device__ float g_v[(size_t)NR * FF];
__device__ float g_x[(size_t)NR * FF];
__device__ int   g_mask_byte_mode;

// ---------------- mask dtype classifier ----------------
// bool mask may be serialized as int32 (words 0/1), float32 (0.0/1.0f ==
// 0x3F800000), or packed 1-byte bool. Classify from the first 4KB:
//   any word == 0x3F800000 -> float32 (4-byte nonzero test)
//   else any word > 1      -> packed bytes (1-byte nonzero test)
//   else                   -> int32 (4-byte nonzero test)
__global__ void detect_mask_kernel(const unsigned int* __restrict__ mask) {
    __shared__ int has_f, has_big;
    if (threadIdx.x == 0) { has_f = 0; has_big = 0; }
    __syncthreads();
    #pragma unroll
    for (int u = 0; u < 4; u++) {
        unsigned int w = mask[threadIdx.x * 4 + u];
        if (w == 0x3F800000u) atomicOr(&has_f, 1);
        else if (w > 1u)      atomicOr(&has_big, 1);
    }
    __syncthreads();
    if (threadIdx.x == 0)
        g_mask_byte_mode = (!has_f && has_big) ? 1 : 0;
}

// ---------------- QKV projections: C = A @ W + bias, M=4096 N=1024 K=1024 ----------------
__global__ __launch_bounds__(256) void gemm_proj_kernel(
    const float* __restrict__ q_in, const float* __restrict__ k_in,
    const float* __restrict__ v_in,
    const float* __restrict__ Wq, const float* __restrict__ bq,
    const float* __restrict__ Wk, const float* __restrict__ bk,
    const float* __restrict__ Wv, const float* __restrict__ bv)
{
    const float *A, *W, *bias; float *C;
    if (blockIdx.z == 0)      { A = q_in; W = Wq; bias = bq; C = g_q; }
    else if (blockIdx.z == 1) { A = k_in; W = Wk; bias = bk; C = g_k; }
    else                      { A = v_in; W = Wv; bias = bv; C = g_v; }

    __shared__ float As[16][128];
    __shared__ float Bs[16][128];

    const int K = FF, N = FF;
    int tid = threadIdx.x;
    int bn = blockIdx.x * 128;
    int bm = blockIdx.y * 128;
    int tx = tid & 15, ty = tid >> 4;

    float acc[8][8];
    #pragma unroll
    for (int i = 0; i < 8; i++)
        #pragma unroll
        for (int j = 0; j < 8; j++) acc[i][j] = 0.f;

    int ar = tid >> 2;            // 0..63
    int ac = (tid & 3) << 2;      // 0,4,8,12
    int br = tid >> 5;            // 0..7
    int bc = (tid & 31) << 2;     // 0..124

    for (int k0 = 0; k0 < K; k0 += 16) {
        float4 a0 = *(const float4*)(A + (size_t)(bm + ar)      * K + k0 + ac);
        float4 a1 = *(const float4*)(A + (size_t)(bm + ar + 64) * K + k0 + ac);
        As[ac+0][ar]    = a0.x; As[ac+1][ar]    = a0.y; As[ac+2][ar]    = a0.z; As[ac+3][ar]    = a0.w;
        As[ac+0][ar+64] = a1.x; As[ac+1][ar+64] = a1.y; As[ac+2][ar+64] = a1.z; As[ac+3][ar+64] = a1.w;
        *(float4*)&Bs[br][bc]   = *(const float4*)(W + (size_t)(k0 + br)     * N + bn + bc);
        *(float4*)&Bs[br+8][bc] = *(const float4*)(W + (size_t)(k0 + br + 8) * N + bn + bc);
        __syncthreads();
        #pragma unroll
        for (int kk = 0; kk < 16; kk++) {
            float ra[8], rb[8];
            *(float4*)&ra[0] = *(const float4*)&As[kk][ty*8];
            *(float4*)&ra[4] = *(const float4*)&As[kk][ty*8+4];
            *(float4*)&rb[0] = *(const float4*)&Bs[kk][tx*8];
            *(float4*)&rb[4] = *(const float4*)&Bs[kk][tx*8+4];
            #pragma unroll
            for (int i = 0; i < 8; i++)
                #pragma unroll
                for (int j = 0; j < 8; j++)
                    acc[i][j] = fmaf(ra[i], rb[j], acc[i][j]);
        }
        __syncthreads();
    }
    #pragma unroll
    for (int i = 0; i < 8; i++) {
        size_t row = (size_t)(bm + ty*8 + i);
        const float* bp = bias + bn + tx*8;
        float4 o0, o1;
        o0.x = acc[i][0] + bp[0]; o0.y = acc[i][1] + bp[1];
        o0.z = acc[i][2] + bp[2]; o0.w = acc[i][3] + bp[3];
        o1.x = acc[i][4] + bp[4]; o1.y = acc[i][5] + bp[5];
        o1.z = acc[i][6] + bp[6]; o1.w = acc[i][7] + bp[7];
        *(float4*)(C + row * N + bn + tx*8)     = o0;
        *(float4*)(C + row * N + bn + tx*8 + 4) = o1;
    }
}

// ---------------- scores: S[hb,i,j] = (Q_h . K_h) / 8, NT-GEMM K=64 ----------------
__global__ __launch_bounds__(256) void scores_kernel(float* __restrict__ attn)
{
    int hb = blockIdx.z, h = hb >> 2, b = hb & 3;
    int i0 = blockIdx.y * 64, j0 = blockIdx.x * 64;
    __shared__ float Qs[64][65];
    __shared__ float Ks[64][65];

    int tid = threadIdx.x;
    int lr = tid >> 2;            // 0..63
    int lc = (tid & 3) << 4;      // 0,16,32,48
    const float* qb = g_q + ((size_t)(b * TT + i0 + lr)) * FF + h * DD;
    const float* kb = g_k + ((size_t)(b * TT + j0 + lr)) * FF + h * DD;
    #pragma unroll
    for (int u = 0; u < 16; u += 4) {
        float4 qa = *(const float4*)(qb + lc + u);
        Qs[lr][lc+u] = qa.x; Qs[lr][lc+u+1] = qa.y; Qs[lr][lc+u+2] = qa.z; Qs[lr][lc+u+3] = qa.w;
        float4 ka = *(const float4*)(kb + lc + u);
        Ks[lr][lc+u] = ka.x; Ks[lr][lc+u+1] = ka.y; Ks[lr][lc+u+2] = ka.z; Ks[lr][lc+u+3] = ka.w;
    }
    __syncthreads();

    int tx = tid & 15, ty = tid >> 4;
    float acc[4][4];
    #pragma unroll
    for (int i = 0; i < 4; i++)
        #pragma unroll
        for (int j = 0; j < 4; j++) acc[i][j] = 0.f;

    #pragma unroll
    for (int d = 0; d < 64; d++) {
        float ra[4], rb[4];
        #pragma unroll
        for (int ii = 0; ii < 4; ii++) ra[ii] = Qs[ty*4+ii][d];
        #pragma unroll
        for (int jj = 0; jj < 4; jj++) rb[jj] = Ks[tx*4+jj][d];
        #pragma unroll
        for (int ii = 0; ii < 4; ii++)
            #pragma unroll
            for (int jj = 0; jj < 4; jj++)
                acc[ii][jj] = fmaf(ra[ii], rb[jj], acc[ii][jj]);
    }
    #pragma unroll
    for (int ii = 0; ii < 4; ii++) {
        size_t row = (size_t)hb * TT + i0 + ty*4 + ii;
        float4 o;
        o.x = acc[ii][0] * 0.125f; o.y = acc[ii][1] * 0.125f;
        o.z = acc[ii][2] * 0.125f; o.w = acc[ii][3] * 0.125f;
        *(float4*)(attn + row * TT + j0 + tx*4) = o;
    }
}

// ---------------- masked softmax (in place on attn region) ----------------
__global__ __launch_bounds__(256) void softmax_kernel(
    float* __restrict__ attn, const unsigned int* __restrict__ mask,
    const float* __restrict__ qmask)
{
    const float NEG = -FLT_MAX;
    int r = blockIdx.x;                    // 0..65535 = hb*1024 + i
    size_t base = (size_t)r * TT;
    int hb = r >> 10;
    int i  = r & (TT - 1);
    int b  = hb & 3;
    int t  = threadIdx.x;

    float4 s = *(const float4*)(attn + base + t*4);

    unsigned int m0, m1, m2, m3;
    if (g_mask_byte_mode) {
        const unsigned char* mb = (const unsigned char*)mask;
        uchar4 mc = *(const uchar4*)(mb + base + t*4);
        m0 = mc.x; m1 = mc.y; m2 = mc.z; m3 = mc.w;
    } else {
        uint4 mv = *(const uint4*)(mask + base + t*4);
        m0 = mv.x; m1 = mv.y; m2 = mv.z; m3 = mv.w;
    }

    float v0 = m0 ? NEG : s.x;
    float v1 = m1 ? NEG : s.y;
    float v2 = m2 ? NEG : s.z;
    float v3 = m3 ? NEG : s.w;
    float lm = fmaxf(fmaxf(v0, v1), fmaxf(v2, v3));

    __shared__ float red[8];
    int wid = t >> 5, lane = t & 31;
    #pragma unroll
    for (int o = 16; o; o >>= 1) lm = fmaxf(lm, __shfl_xor_sync(0xFFFFFFFFu, lm, o));
    if (lane == 0) red[wid] = lm;
    __syncthreads();
    float gmax = fmaxf(fmaxf(fmaxf(red[0], red[1]), fmaxf(red[2], red[3])),
                       fmaxf(fmaxf(red[4], red[5]), fmaxf(red[6], red[7])));

    float e0 = m0 ? 0.f : __expf(s.x - gmax);
    float e1 = m1 ? 0.f : __expf(s.y - gmax);
    float e2 = m2 ? 0.f : __expf(s.z - gmax);
    float e3 = m3 ? 0.f : __expf(s.w - gmax);
    float ls = (e0 + e1) + (e2 + e3);
    #pragma unroll
    for (int o = 16; o; o >>= 1) ls += __shfl_xor_sync(0xFFFFFFFFu, ls, o);
    __syncthreads();               // red reuse safe
    if (lane == 0) red[wid] = ls;
    __syncthreads();
    float gsum = ((red[0] + red[1]) + (red[2] + red[3])) +
                 ((red[4] + red[5]) + (red[6] + red[7]));

    float scale = qmask[b * TT + i] / gsum;
    float4 o;
    o.x = e0 * scale; o.y = e1 * scale; o.z = e2 * scale; o.w = e3 * scale;
    *(float4*)(attn + base + t*4) = o;
}

// ---------------- x = attn @ V per (h,b): M=1024 N=64 K=1024 ----------------
__global__ __launch_bounds__(256) void av_kernel(const float* __restrict__ attn)
{
    int hb = blockIdx.y, h = hb >> 2, b = hb & 3;
    int i0 = blockIdx.x * 64;
    __shared__ float As[64][65];
    __shared__ float Vs[64][65];

    int tid = threadIdx.x;
    int lr = tid >> 2;
    int lc = (tid & 3) << 4;
    int tx = tid & 15, ty = tid >> 4;

    float acc[4][4];
    #pragma unroll
    for (int i = 0; i < 4; i++)
        #pragma unroll
        for (int j = 0; j < 4; j++) acc[i][j] = 0.f;

    for (int j0 = 0; j0 < TT; j0 += 64) {
        const float* ab = attn + ((size_t)hb * TT + i0 + lr) * TT + j0;
        const float* vb = g_v + ((size_t)(b * TT + j0 + lr)) * FF + h * DD;
        #pragma unroll
        for (int u = 0; u < 16; u += 4) {
            float4 aa = *(const float4*)(ab + lc + u);
            As[lr][lc+u] = aa.x; As[lr][lc+u+1] = aa.y; As[lr][lc+u+2] = aa.z; As[lr][lc+u+3] = aa.w;
            float4 va = *(const float4*)(vb + lc + u);
            Vs[lr][lc+u] = va.x; Vs[lr][lc+u+1] = va.y; Vs[lr][lc+u+2] = va.z; Vs[lr][lc+u+3] = va.w;
        }
        __syncthreads();
        #pragma unroll
        for (int kk = 0; kk < 64; kk++) {
            float ra[4], rb[4];
            #pragma unroll
            for (int ii = 0; ii < 4; ii++) ra[ii] = As[ty*4+ii][kk];
            #pragma unroll
            for (int jj = 0; jj < 4; jj++) rb[jj] = Vs[kk][tx*4+jj];
            #pragma unroll
            for (int ii = 0; ii < 4; ii++)
                #pragma unroll
                for (int jj = 0; jj < 4; jj++)
                    acc[ii][jj] = fmaf(ra[ii], rb[jj], acc[ii][jj]);
        }
        __syncthreads();
    }
    #pragma unroll
    for (int ii = 0; ii < 4; ii++) {
        size_t row = (size_t)(b * TT + i0 + ty*4 + ii);
        float4 o;
        o.x = acc[ii][0]; o.y = acc[ii][1]; o.z = acc[ii][2]; o.w = acc[ii][3];
        *(float4*)(g_x + row * FF + h * DD + tx*4) = o;
    }
}

// ---------------- out = concat(x, query) @ Wf + bf + query ----------------
__global__ __launch_bounds__(256) void gemm_final_kernel(
    const float* __restrict__ query, const float* __restrict__ Wf,
    const float* __restrict__ bf, float* __restrict__ out)
{
    __shared__ float As[16][128];
    __shared__ float Bs[16][128];

    const int K = 2 * FF, N = FF;
    int tid = threadIdx.x;
    int bn = blockIdx.x * 128;
    int bm = blockIdx.y * 128;
    int tx = tid & 15, ty = tid >> 4;

    float acc[8][8];
    #pragma unroll
    for (int i = 0; i < 8; i++)
        #pragma unroll
        for (int j = 0; j < 8; j++) acc[i][j] = 0.f;

    int ar = tid >> 2;
    int ac = (tid & 3) << 2;
    int br = tid >> 5;
    int bc = (tid & 31) << 2;

    for (int k0 = 0; k0 < K; k0 += 16) {
        int col = k0 + ac;
        float4 a0, a1;
        if (col < FF) {
            a0 = *(const float4*)(g_x + (size_t)(bm + ar)      * FF + col);
            a1 = *(const float4*)(g_x + (size_t)(bm + ar + 64) * FF + col);
        } else {
            a0 = *(const float4*)(query + (size_t)(bm + ar)      * FF + (col - FF));
            a1 = *(const float4*)(query + (size_t)(bm + ar + 64) * FF + (col - FF));
        }
        As[ac+0][ar]    = a0.x; As[ac+1][ar]    = a0.y; As[ac+2][ar]    = a0.z; As[ac+3][ar]    = a0.w;
        As[ac+0][ar+64] = a1.x; As[ac+1][ar+64] = a1.y; As[ac+2][ar+64] = a1.z; As[ac+3][ar+64] = a1.w;
        *(float4*)&Bs[br][bc]   = *(const float4*)(Wf + (size_t)(k0 + br)     * N + bn + bc);
        *(float4*)&Bs[br+8][bc] = *(const float4*)(Wf + (size_t)(k0 + br + 8) * N + bn + bc);
        __syncthreads();
        #pragma unroll
        for (int kk = 0; kk < 16; kk++) {
            float ra[8], rb[8];
            *(float4*)&ra[0] = *(const float4*)&As[kk][ty*8];
            *(float4*)&ra[4] = *(const float4*)&As[kk][ty*8+4];
            *(float4*)&rb[0] = *(const float4*)&Bs[kk][tx*8];
            *(float4*)&rb[4] = *(const float4*)&Bs[kk][tx*8+4];
            #pragma unroll
            for (int i = 0; i < 8; i++)
                #pragma unroll
                for (int j = 0; j < 8; j++)
                    acc[i][j] = fmaf(ra[i], rb[j], acc[i][j]);
        }
        __syncthreads();
    }
    #pragma unroll
    for (int i = 0; i < 8; i++) {
        size_t row = (size_t)(bm + ty*8 + i);
        const float* bp = bf + bn + tx*8;
        const float* rp = query + row * FF + bn + tx*8;
        float4 o0, o1;
        o0.x = acc[i][0] + bp[0] + rp[0]; o0.y = acc[i][1] + bp[1] + rp[1];
        o0.z = acc[i][2] + bp[2] + rp[2]; o0.w = acc[i][3] + bp[3] + rp[3];
        o1.x = acc[i][4] + bp[4] + rp[4]; o1.y = acc[i][5] + bp[5] + rp[5];
        o1.z = acc[i][6] + bp[6] + rp[6]; o1.w = acc[i][7] + bp[7] + rp[7];
        *(float4*)(out + row * N + bn + tx*8)     = o0;
        *(float4*)(out + row * N + bn + tx*8 + 4) = o1;
    }
}

// ---------------- launch ----------------
extern "C" void kernel_launch(void* const* d_in, const int* in_sizes, int n_in,
                              void* d_out, int out_size)
{
    const float* query = (const float*)d_in[0];
    const float* key   = (const float*)d_in[1];
    const float* value = (const float*)d_in[2];
    const unsigned int* mask = (const unsigned int*)d_in[3];
    const float* qmask = (const float*)d_in[4];
    const float* Wq = (const float*)d_in[5];
    const float* bq = (const float*)d_in[6];
    const float* Wk = (const float*)d_in[7];
    const float* bk = (const float*)d_in[8];
    const float* Wv = (const float*)d_in[9];
    const float* bv = (const float*)d_in[10];
    const float* Wf = (const float*)d_in[11];
    const float* bf = (const float*)d_in[12];

    float* out  = (float*)d_out;
    float* attn = out + (size_t)NR * FF;   // out (4,1024,1024) then attn (64,1024,1024)

    detect_mask_kernel<<<1, 256>>>(mask);
    gemm_proj_kernel<<<dim3(8, 32, 3), 256>>>(query, key, value, Wq, bq, Wk, bk, Wv, bv);
    scores_kernel<<<dim3(16, 16, 64), 256>>>(attn);
    softmax_kernel<<<dim3(HH * BB * TT), 256>>>(attn, mask, qmask);
    av_kernel<<<dim3(16, 64), 256>>>(attn);
    gemm_final_kernel<<<dim3(8, 32), 256>>>(query, Wf, bf, out);
}

// round 2
// speedup vs baseline: 1.6935x; 1.6935x over previous
#include <cuda_runtime.h>
#include <math.h>
#include <float.h>

#define BB 4
#define TT 1024
#define FF 1024
#define HH 16
#define DD 64
#define NR (BB*TT)        // 4096

// ---------------- scratch ----------------
__device__ float g_q[(size_t)NR * FF];
__device__ float g_k[(size_t)NR * FF];
__device__ float g_v[(size_t)NR * FF];
__device__ float g_x[(size_t)NR * FF];
__device__ float g_rowscale[HH * BB * TT];
__device__ int   g_mask_byte_mode;

// ---------------- helpers ----------------
__device__ __forceinline__ unsigned f2tf(float x) {
    unsigned r; asm("cvt.rna.tf32.f32 %0, %1;" : "=r"(r) : "f"(x)); return r;
}
__device__ __forceinline__ float f2tf_f(float x) {
    return __uint_as_float(f2tf(x));
}
__device__ __forceinline__ void mma8(float c[4], const unsigned a[4], const unsigned b[2]) {
    asm("mma.sync.aligned.m16n8k8.row.col.f32.tf32.tf32.f32 "
        "{%0,%1,%2,%3},{%4,%5,%6,%7},{%8,%9},{%0,%1,%2,%3};"
        : "+f"(c[0]), "+f"(c[1]), "+f"(c[2]), "+f"(c[3])
        : "r"(a[0]), "r"(a[1]), "r"(a[2]), "r"(a[3]), "r"(b[0]), "r"(b[1]));
}

// ---------------- mask dtype classifier ----------------
__global__ void detect_mask_kernel(const unsigned int* __restrict__ mask) {
    __shared__ int has_f, has_big;
    if (threadIdx.x == 0) { has_f = 0; has_big = 0; }
    __syncthreads();
    #pragma unroll
    for (int u = 0; u < 4; u++) {
        unsigned int w = mask[threadIdx.x * 4 + u];
        if (w == 0x3F800000u) atomicOr(&has_f, 1);
        else if (w > 1u)      atomicOr(&has_big, 1);
    }
    __syncthreads();
    if (threadIdx.x == 0)
        g_mask_byte_mode = (!has_f && has_big) ? 1 : 0;
}

// ---------------- QKV projections via tf32 mma, Q/K with hi+lo split ----------------
#define APAD 20
#define BPAD 136
__global__ __launch_bounds__(256) void proj_tf32_kernel(
    const float* __restrict__ q_in, const float* __restrict__ k_in,
    const float* __restrict__ v_in,
    const float* __restrict__ Wq, const float* __restrict__ bq,
    const float* __restrict__ Wk, const float* __restrict__ bk,
    const float* __restrict__ Wv, const float* __restrict__ bv)
{
    const float *A, *W, *bias; float *C; bool split;
    if (blockIdx.z == 0)      { A = q_in; W = Wq; bias = bq; C = g_q; split = true; }
    else if (blockIdx.z == 1) { A = k_in; W = Wk; bias = bk; C = g_k; split = true; }
    else                      { A = v_in; W = Wv; bias = bv; C = g_v; split = false; }

    __shared__ float Ah[128][APAD], Al[128][APAD];
    __shared__ float Bh[16][BPAD],  Bl[16][BPAD];

    int tid = threadIdx.x, lane = tid & 31, warp = tid >> 5;
    int wm = (warp >> 2) * 64, wn = (warp & 3) * 32;
    int bm = blockIdx.y * 128, bn = blockIdx.x * 128;

    float acc[4][4][4];
    #pragma unroll
    for (int i = 0; i < 4; i++)
        #pragma unroll
        for (int j = 0; j < 4; j++)
            #pragma unroll
            for (int r = 0; r < 4; r++) acc[i][j][r] = 0.f;

    for (int k0 = 0; k0 < FF; k0 += 16) {
        #pragma unroll
        for (int u = 0; u < 2; u++) {
            int s = tid + u * 256;
            int r  = s >> 2, c4 = (s & 3) * 4;
            float4 av = *(const float4*)(A + (size_t)(bm + r) * FF + k0 + c4);
            float4 hi, lo;
            hi.x = f2tf_f(av.x); lo.x = f2tf_f(av.x - hi.x);
            hi.y = f2tf_f(av.y); lo.y = f2tf_f(av.y - hi.y);
            hi.z = f2tf_f(av.z); lo.z = f2tf_f(av.z - hi.z);
            hi.w = f2tf_f(av.w); lo.w = f2tf_f(av.w - hi.w);
            *(float4*)&Ah[r][c4] = hi;
            *(float4*)&Al[r][c4] = lo;

            int rb = s >> 5, cb = (s & 31) * 4;
            float4 bv4 = *(const float4*)(W + (size_t)(k0 + rb) * FF + bn + cb);
            float4 bhi, blo;
            bhi.x = f2tf_f(bv4.x); blo.x = f2tf_f(bv4.x - bhi.x);
            bhi.y = f2tf_f(bv4.y); blo.y = f2tf_f(bv4.y - bhi.y);
            bhi.z = f2tf_f(bv4.z); blo.z = f2tf_f(bv4.z - bhi.z);
            bhi.w = f2tf_f(bv4.w); blo.w = f2tf_f(bv4.w - bhi.w);
            *(float4*)&Bh[rb][cb] = bhi;
            *(float4*)&Bl[rb][cb] = blo;
        }
        __syncthreads();
        #pragma unroll
        for (int ks = 0; ks < 16; ks += 8) {
            unsigned ah[4][4], bh[4][2];
            #pragma unroll
            for (int mt = 0; mt < 4; mt++) {
                int r = wm + mt * 16 + (lane >> 2);
                int k = ks + (lane & 3);
                ah[mt][0] = __float_as_uint(Ah[r][k]);
                ah[mt][1] = __float_as_uint(Ah[r + 8][k]);
                ah[mt][2] = __float_as_uint(Ah[r][k + 4]);
                ah[mt][3] = __float_as_uint(Ah[r + 8][k + 4]);
            }
            #pragma unroll
            for (int nt = 0; nt < 4; nt++) {
                int k = ks + (lane & 3);
                int n = wn + nt * 8 + (lane >> 2);
                bh[nt][0] = __float_as_uint(Bh[k][n]);
                bh[nt][1] = __float_as_uint(Bh[k + 4][n]);
            }
            #pragma unroll
            for (int mt = 0; mt < 4; mt++)
                #pragma unroll
                for (int nt = 0; nt < 4; nt++)
                    mma8(acc[mt][nt], ah[mt], bh[nt]);
            if (split) {
                unsigned al[4][4], bl[4][2];
                #pragma unroll
                for (int mt = 0; mt < 4; mt++) {
                    int r = wm + mt * 16 + (lane >> 2);
                    int k = ks + (lane & 3);
                    al[mt][0] = __float_as_uint(Al[r][k]);
                    al[mt][1] = __float_as_uint(Al[r + 8][k]);
                    al[mt][2] = __float_as_uint(Al[r][k + 4]);
                    al[mt][3] = __float_as_uint(Al[r + 8][k + 4]);
                }
                #pragma unroll
                for (int nt = 0; nt < 4; nt++) {
                    int k = ks + (lane & 3);
                    int n = wn + nt * 8 + (lane >> 2);
                    bl[nt][0] = __float_as_uint(Bl[k][n]);
                    bl[nt][1] = __float_as_uint(Bl[k + 4][n]);
                }
                #pragma unroll
                for (int mt = 0; mt < 4; mt++)
                    #pragma unroll
                    for (int nt = 0; nt < 4; nt++) {
                        mma8(acc[mt][nt], ah[mt], bl[nt]);
                        mma8(acc[mt][nt], al[mt], bh[nt]);
                    }
            }
        }
        __syncthreads();
    }
    #pragma unroll
    for (int mt = 0; mt < 4; mt++) {
        int r = bm + wm + mt * 16 + (lane >> 2);
        #pragma unroll
        for (int nt = 0; nt < 4; nt++) {
            int cc = bn + wn + nt * 8 + 2 * (lane & 3);
            float b0 = bias[cc], b1 = bias[cc + 1];
            float2 o0 = make_float2(acc[mt][nt][0] + b0, acc[mt][nt][1] + b1);
            float2 o1 = make_float2(acc[mt][nt][2] + b0, acc[mt][nt][3] + b1);
            *(float2*)(C + (size_t)r * FF + cc)       = o0;
            *(float2*)(C + (size_t)(r + 8) * FF + cc) = o1;
        }
    }
}

// ---------------- fused attention: S (split tf32) + mask + exp + AV, unnormalized ----------------
#define EPAD 68
#define ATT_SMEM ((6 * 64 * EPAD + 64) * 4)
__global__ __launch_bounds__(256) void attn_fused_kernel(
    float* __restrict__ attn, const unsigned int* __restrict__ mask,
    const float* __restrict__ qmask)
{
    extern __shared__ float sm[];
    float* Qh   = sm;
    float* Ql   = Qh + 64 * EPAD;
    float* Kh   = Ql + 64 * EPAD;
    float* Kl   = Kh + 64 * EPAD;
    float* Vs   = Kl + 64 * EPAD;
    float* Es   = Vs + 64 * EPAD;
    float* lsum = Es + 64 * EPAD;

    int tid = threadIdx.x, lane = tid & 31, warp = tid >> 5;
    int hb = blockIdx.y, h = hb >> 2, b = hb & 3;
    int i0 = blockIdx.x * 64;
    int wm = (warp >> 2) * 32, wn = (warp & 3) * 16;
    int bytemode = g_mask_byte_mode;

    // load Q tile (64x64), split hi/lo
    #pragma unroll
    for (int u = 0; u < 4; u++) {
        int s = tid + u * 256;
        int r = s >> 4, c4 = (s & 15) * 4;
        float4 qv = *(const float4*)(g_q + (size_t)(b * TT + i0 + r) * FF + h * DD + c4);
        float4 hi, lo;
        hi.x = f2tf_f(qv.x); lo.x = f2tf_f(qv.x - hi.x);
        hi.y = f2tf_f(qv.y); lo.y = f2tf_f(qv.y - hi.y);
        hi.z = f2tf_f(qv.z); lo.z = f2tf_f(qv.z - hi.z);
        hi.w = f2tf_f(qv.w); lo.w = f2tf_f(qv.w - hi.w);
        *(float4*)&Qh[r * EPAD + c4] = hi;
        *(float4*)&Ql[r * EPAD + c4] = lo;
    }
    if (tid < 64) lsum[tid] = 0.f;

    float X[2][2][4];
    #pragma unroll
    for (int i = 0; i < 2; i++)
        #pragma unroll
        for (int j = 0; j < 2; j++)
            #pragma unroll
            for (int r = 0; r < 4; r++) X[i][j][r] = 0.f;

    __syncthreads();

    for (int j0 = 0; j0 < TT; j0 += 64) {
        // load K (split) and V (tf32-rounded)
        #pragma unroll
        for (int u = 0; u < 4; u++) {
            int s = tid + u * 256;
            int r = s >> 4, c4 = (s & 15) * 4;
            float4 kv = *(const float4*)(g_k + (size_t)(b * TT + j0 + r) * FF + h * DD + c4);
            float4 hi, lo;
            hi.x = f2tf_f(kv.x); lo.x = f2tf_f(kv.x - hi.x);
            hi.y = f2tf_f(kv.y); lo.y = f2tf_f(kv.y - hi.y);
            hi.z = f2tf_f(kv.z); lo.z = f2tf_f(kv.z - hi.z);
            hi.w = f2tf_f(kv.w); lo.w = f2tf_f(kv.w - hi.w);
            *(float4*)&Kh[r * EPAD + c4] = hi;
            *(float4*)&Kl[r * EPAD + c4] = lo;
            float4 vv = *(const float4*)(g_v + (size_t)(b * TT + j0 + r) * FF + h * DD + c4);
            float4 vh;
            vh.x = f2tf_f(vv.x); vh.y = f2tf_f(vv.y);
            vh.z = f2tf_f(vv.z); vh.w = f2tf_f(vv.w);
            *(float4*)&Vs[r * EPAD + c4] = vh;
        }
        __syncthreads();

        // S = Q @ K^T (3-pass split tf32)
        float sacc[2][2][4];
        #pragma unroll
        for (int i = 0; i < 2; i++)
            #pragma unroll
            for (int j = 0; j < 2; j++)
                #pragma unroll
                for (int r = 0; r < 4; r++) sacc[i][j][r] = 0.f;

        #pragma unroll
        for (int ks = 0; ks < 64; ks += 8) {
            unsigned ah[2][4], al[2][4], bh[2][2], bl[2][2];
            #pragma unroll
            for (int mt = 0; mt < 2; mt++) {
                int r = wm + mt * 16 + (lane >> 2);
                int k = ks + (lane & 3);
                ah[mt][0] = __float_as_uint(Qh[r * EPAD + k]);
                ah[mt][1] = __float_as_uint(Qh[(r + 8) * EPAD + k]);
                ah[mt][2] = __float_as_uint(Qh[r * EPAD + k + 4]);
                ah[mt][3] = __float_as_uint(Qh[(r + 8) * EPAD + k + 4]);
                al[mt][0] = __float_as_uint(Ql[r * EPAD + k]);
                al[mt][1] = __float_as_uint(Ql[(r + 8) * EPAD + k]);
                al[mt][2] = __float_as_uint(Ql[r * EPAD + k + 4]);
                al[mt][3] = __float_as_uint(Ql[(r + 8) * EPAD + k + 4]);
            }
            #pragma unroll
            for (int nt = 0; nt < 2; nt++) {
                int n = wn + nt * 8 + (lane >> 2);
                int k = ks + (lane & 3);
                bh[nt][0] = __float_as_uint(Kh[n * EPAD + k]);
                bh[nt][1] = __float_as_uint(Kh[n * EPAD + k + 4]);
                bl[nt][0] = __float_as_uint(Kl[n * EPAD + k]);
                bl[nt][1] = __float_as_uint(Kl[n * EPAD + k + 4]);
            }
            #pragma unroll
            for (int mt = 0; mt < 2; mt++)
                #pragma unroll
                for (int nt = 0; nt < 2; nt++) {
                    mma8(sacc[mt][nt], ah[mt], bh[nt]);
                    mma8(sacc[mt][nt], ah[mt], bl[nt]);
                    mma8(sacc[mt][nt], al[mt], bh[nt]);
                }
        }

        // mask + exp + write unnormalized attn + stage e in smem
        #pragma unroll
        for (int mt = 0; mt < 2; mt++) {
            #pragma unroll
            for (int nt = 0; nt < 2; nt++) {
                int ri = wm + mt * 16 + (lane >> 2);
                int cj = wn + nt * 8 + 2 * (lane & 3);
                size_t gi0 = ((size_t)hb * TT + i0 + ri) * TT + j0 + cj;
                size_t gi1 = gi0 + (size_t)8 * TT;
                unsigned m00, m01, m10, m11;
                if (bytemode) {
                    const unsigned char* mb = (const unsigned char*)mask;
                    m00 = mb[gi0]; m01 = mb[gi0 + 1];
                    m10 = mb[gi1]; m11 = mb[gi1 + 1];
                } else {
                    m00 = mask[gi0]; m01 = mask[gi0 + 1];
                    m10 = mask[gi1]; m11 = mask[gi1 + 1];
                }
                float e00 = m00 ? 0.f : __expf(sacc[mt][nt][0] * 0.125f);
                float e01 = m01 ? 0.f : __expf(sacc[mt][nt][1] * 0.125f);
                float e10 = m10 ? 0.f : __expf(sacc[mt][nt][2] * 0.125f);
                float e11 = m11 ? 0.f : __expf(sacc[mt][nt][3] * 0.125f);
                *(float2*)(attn + gi0) = make_float2(e00, e01);
                *(float2*)(attn + gi1) = make_float2(e10, e11);
                Es[ri * EPAD + cj]           = e00;
                Es[ri * EPAD + cj + 1]       = e01;
                Es[(ri + 8) * EPAD + cj]     = e10;
                Es[(ri + 8) * EPAD + cj + 1] = e11;
            }
        }
        __syncthreads();

        // row sums (full precision e)
        {
            int r = tid >> 2, seg = (tid & 3) * 16;
            float p = 0.f;
            #pragma unroll
            for (int t = 0; t < 16; t++) p += Es[r * EPAD + seg + t];
            p += __shfl_xor_sync(0xFFFFFFFFu, p, 1);
            p += __shfl_xor_sync(0xFFFFFFFFu, p, 2);
            if ((tid & 3) == 0) lsum[r] += p;
        }

        // X += E @ V (single tf32)
        #pragma unroll
        for (int ks = 0; ks < 64; ks += 8) {
            unsigned ae[2][4], bv[2][2];
            #pragma unroll
            for (int mt = 0; mt < 2; mt++) {
                int r = wm + mt * 16 + (lane >> 2);
                int k = ks + (lane & 3);
                ae[mt][0] = f2tf(Es[r * EPAD + k]);
                ae[mt][1] = f2tf(Es[(r + 8) * EPAD + k]);
                ae[mt][2] = f2tf(Es[r * EPAD + k + 4]);
                ae[mt][3] = f2tf(Es[(r + 8) * EPAD + k + 4]);
            }
            #pragma unroll
            for (int nt = 0; nt < 2; nt++) {
                int n = wn + nt * 8 + (lane >> 2);
                int k = ks + (lane & 3);
                bv[nt][0] = __float_as_uint(Vs[k * EPAD + n]);
                bv[nt][1] = __float_as_uint(Vs[(k + 4) * EPAD + n]);
            }
            #pragma unroll
            for (int mt = 0; mt < 2; mt++)
                #pragma unroll
                for (int nt = 0; nt < 2; nt++)
                    mma8(X[mt][nt], ae[mt], bv[nt]);
        }
        __syncthreads();
    }

    // epilogue: x = X * qmask / l; and per-row scale for normalize pass
    #pragma unroll
    for (int mt = 0; mt < 2; mt++) {
        int ri = wm + mt * 16 + (lane >> 2);
        float sc0 = qmask[b * TT + i0 + ri]     / lsum[ri];
        float sc1 = qmask[b * TT + i0 + ri + 8] / lsum[ri + 8];
        #pragma unroll
        for (int nt = 0; nt < 2; nt++) {
            int d = wn + nt * 8 + 2 * (lane & 3);
            float2 o0 = make_float2(X[mt][nt][0] * sc0, X[mt][nt][1] * sc0);
            float2 o1 = make_float2(X[mt][nt][2] * sc1, X[mt][nt][3] * sc1);
            *(float2*)(g_x + (size_t)(b * TT + i0 + ri) * FF + h * DD + d)     = o0;
            *(float2*)(g_x + (size_t)(b * TT + i0 + ri + 8) * FF + h * DD + d) = o1;
        }
    }
    if (tid < 64)
        g_rowscale[hb * TT + i0 + tid] = qmask[b * TT + i0 + tid] / lsum[tid];
}

// ---------------- normalize attn in place ----------------
__global__ __launch_bounds__(256) void normalize_kernel(float* __restrict__ attn)
{
    int row = blockIdx.x;
    float s = g_rowscale[row];
    float4* p = (float4*)(attn + (size_t)row * TT) + threadIdx.x;
    float4 v = *p;
    v.x *= s; v.y *= s; v.z *= s; v.w *= s;
    *p = v;
}

// ---------------- final: out = concat(x, query) @ Wf + bf + query (single tf32) ----------------
__global__ __launch_bounds__(256) void final_tf32_kernel(
    const float* __restrict__ query, const float* __restrict__ Wf,
    const float* __restrict__ bf, float* __restrict__ out)
{
    __shared__ float Ah[128][APAD];
    __shared__ float Bh[16][BPAD];

    const int K = 2 * FF;
    int tid = threadIdx.x, lane = tid & 31, warp = tid >> 5;
    int wm = (warp >> 2) * 64, wn = (warp & 3) * 32;
    int bm = blockIdx.y * 128, bn = blockIdx.x * 128;

    float acc[4][4][4];
    #pragma unroll
    for (int i = 0; i < 4; i++)
        #pragma unroll
        for (int j = 0; j < 4; j++)
            #pragma unroll
            for (int r = 0; r < 4; r++) acc[i][j][r] = 0.f;

    for (int k0 = 0; k0 < K; k0 += 16) {
        #pragma unroll
        for (int u = 0; u < 2; u++) {
            int s = tid + u * 256;
            int r = s >> 2, c4 = (s & 3) * 4;
            int col = k0 + c4;
            const float* src = (col < FF)
                ? (g_x + (size_t)(bm + r) * FF + col)
                : (query + (size_t)(bm + r) * FF + (col - FF));
            float4 av = *(const float4*)src;
            float4 hi;
            hi.x = f2tf_f(av.x); hi.y = f2tf_f(av.y);
            hi.z = f2tf_f(av.z); hi.w = f2tf_f(av.w);
            *(float4*)&Ah[r][c4] = hi;

            int rb = s >> 5, cb = (s & 31) * 4;
            float4 bv4 = *(const float4*)(Wf + (size_t)(k0 + rb) * FF + bn + cb);
            float4 bhi;
            bhi.x = f2tf_f(bv4.x); bhi.y = f2tf_f(bv4.y);
            bhi.z = f2tf_f(bv4.z); bhi.w = f2tf_f(bv4.w);
            *(float4*)&Bh[rb][cb] = bhi;
        }
        __syncthreads();
        #pragma unroll
        for (int ks = 0; ks < 16; ks += 8) {
            unsigned ah[4][4], bh[4][2];
            #pragma unroll
            for (int mt = 0; mt < 4; mt++) {
                int r = wm + mt * 16 + (lane >> 2);
                int k = ks + (lane & 3);
                ah[mt][0] = __float_as_uint(Ah[r][k]);
                ah[mt][1] = __float_as_uint(Ah[r + 8][k]);
                ah[mt][2] = __float_as_uint(Ah[r][k + 4]);
                ah[mt][3] = __float_as_uint(Ah[r + 8][k + 4]);
            }
            #pragma unroll
            for (int nt = 0; nt < 4; nt++) {
                int k = ks + (lane & 3);
                int n = wn + nt * 8 + (lane >> 2);
                bh[nt][0] = __float_as_uint(Bh[k][n]);
                bh[nt][1] = __float_as_uint(Bh[k + 4][n]);
            }
            #pragma unroll
            for (int mt = 0; mt < 4; mt++)
                #pragma unroll
                for (int nt = 0; nt < 4; nt++)
                    mma8(acc[mt][nt], ah[mt], bh[nt]);
        }
        __syncthreads();
    }
    #pragma unroll
    for (int mt = 0; mt < 4; mt++) {
        int r = bm + wm + mt * 16 + (lane >> 2);
        #pragma unroll
        for (int nt = 0; nt < 4; nt++) {
            int cc = bn + wn + nt * 8 + 2 * (lane & 3);
            float b0 = bf[cc], b1 = bf[cc + 1];
            const float* q0 = query + (size_t)r * FF + cc;
            const float* q1 = query + (size_t)(r + 8) * FF + cc;
            float2 o0 = make_float2(acc[mt][nt][0] + b0 + q0[0],
                                    acc[mt][nt][1] + b1 + q0[1]);
            float2 o1 = make_float2(acc[mt][nt][2] + b0 + q1[0],
                                    acc[mt][nt][3] + b1 + q1[1]);
            *(float2*)(out + (size_t)r * FF + cc)       = o0;
            *(float2*)(out + (size_t)(r + 8) * FF + cc) = o1;
        }
    }
}

// ---------------- launch ----------------
extern "C" void kernel_launch(void* const* d_in, const int* in_sizes, int n_in,
                              void* d_out, int out_size)
{
    const float* query = (const float*)d_in[0];
    const float* key   = (const float*)d_in[1];
    const float* value = (const float*)d_in[2];
    const unsigned int* mask = (const unsigned int*)d_in[3];
    const float* qmask = (const float*)d_in[4];
    const float* Wq = (const float*)d_in[5];
    const float* bq = (const float*)d_in[6];
    const float* Wk = (const float*)d_in[7];
    const float* bk = (const float*)d_in[8];
    const float* Wv = (const float*)d_in[9];
    const float* bv = (const float*)d_in[10];
    const float* Wf = (const float*)d_in[11];
    const float* bf = (const float*)d_in[12];

    float* out  = (float*)d_out;
    float* attn = out + (size_t)NR * FF;

    cudaFuncSetAttribute(attn_fused_kernel,
                         cudaFuncAttributeMaxDynamicSharedMemorySize, ATT_SMEM);

    detect_mask_kernel<<<1, 256>>>(mask);
    proj_tf32_kernel<<<dim3(8, 32, 3), 256>>>(query, key, value, Wq, bq, Wk, bk, Wv, bv);
    attn_fused_kernel<<<dim3(16, 64), 256, ATT_SMEM>>>(attn, mask, qmask);
    normalize_kernel<<<dim3(HH * BB * TT), 256>>>(attn);
    final_tf32_kernel<<<dim3(8, 32), 256>>>(query, Wf, bf, out);
}